// round 14
// baseline (speedup 1.0000x reference)
#include <cuda_runtime.h>
#include <cuda_fp16.h>
#include <cstdint>

// Problem constants
#define NMB 32          // N*M
#define TLEN 300
#define VJ 25
#define CH 64
#define KT 9
#define NSKEL (NMB*TLEN)          // 9600 skeletons

// -------- scratch --------
__device__ __half g_xg[NMB*VJ*TLEN*CH];            // GCN output (nm,v,t,c), fp16
__device__ __align__(16) uint32_t g_w2[KT*CH*36];  // conv W packed [tap][co][p(ci/2)] half2
__device__ __align__(16) uint32_t g_gw2[CH*36];    // GCN W packed [co][q(ci/2)] half2
__device__ __align__(16) uint32_t g_ah2[32*20];    // normalized adjacency fp16 [v][u-pair], padded
__device__ float g_scale[CH];                      // BN fold
__device__ float g_shift[CH];
__device__ unsigned int g_task;                    // fused task queue (reset by prep)
__device__ unsigned int g_done[NMB];               // per-nm GCN completion counters

#define GCN_GROUPS 2400      // 4 skeletons each; 75 per nm
#define CONV_UNITS 1600      // (slab, half); 50 per nm
#define T_TOT 4000
#define FUSED_GRID 444
#define FUSED_THREADS 160

__device__ __forceinline__ void cp_async16(void* dst_smem, const void* src) {
    uint32_t d = (uint32_t)__cvta_generic_to_shared(dst_smem);
    asm volatile("cp.async.ca.shared.global [%0], [%1], 16;" :: "r"(d), "l"(src));
}
#define CP_COMMIT() asm volatile("cp.async.commit_group;")
#define CP_WAIT0()  asm volatile("cp.async.wait_group 0;")

__device__ __forceinline__ void mma_f16(float* d, const uint32_t* a, uint32_t b0, uint32_t b1) {
    asm volatile("mma.sync.aligned.m16n8k16.row.col.f32.f16.f16.f32 "
        "{%0,%1,%2,%3}, {%4,%5,%6,%7}, {%8,%9}, {%0,%1,%2,%3};"
        : "+f"(d[0]), "+f"(d[1]), "+f"(d[2]), "+f"(d[3])
        : "r"(a[0]), "r"(a[1]), "r"(a[2]), "r"(a[3]), "r"(b0), "r"(b1));
}

__device__ __forceinline__ void ldsm_x4(uint32_t* r, uint32_t saddr) {
    asm volatile("ldmatrix.sync.aligned.m8n8.x4.shared.b16 {%0,%1,%2,%3}, [%4];"
        : "=r"(r[0]), "=r"(r[1]), "=r"(r[2]), "=r"(r[3]) : "r"(saddr));
}

__device__ __forceinline__ unsigned ld_acquire(const unsigned* p) {
    unsigned v;
    asm volatile("ld.acquire.gpu.global.u32 %0, [%1];" : "=r"(v) : "l"(p));
    return v;
}

// ============================ prep ============================
__global__ void prep_kernel(const float* __restrict__ adj,
                            const float* __restrict__ gcn_w,
                            const float* __restrict__ conv_w,
                            const float* __restrict__ conv_b,
                            const float* __restrict__ bn_gamma,
                            const float* __restrict__ bn_beta,
                            const float* __restrict__ bn_mean,
                            const float* __restrict__ bn_var) {
    const int tid = threadIdx.x;
    const int gtid = blockIdx.x * blockDim.x + tid;
    const int gstride = gridDim.x * blockDim.x;

    if (blockIdx.x == 0) {
        if (tid == 0) g_task = 0;
        if (tid < NMB) g_done[tid] = 0;
        __shared__ float norm[VJ];
        if (tid < VJ) {
            float s = 0.f;
            for (int u = 0; u < VJ; u++) s += adj[tid*VJ + u];
            norm[tid] = rsqrtf(s);
        }
        __syncthreads();
        for (int i = tid; i < 32*20; i += blockDim.x) {
            int v = i / 20, q = i % 20;
            uint32_t val = 0;
            if (v < VJ && q < 16) {
                int u0 = 2*q, u1 = 2*q + 1;
                float a0 = (u0 < VJ) ? norm[v]*adj[v*VJ+u0]*norm[u0] : 0.f;
                float a1 = (u1 < VJ) ? norm[v]*adj[v*VJ+u1]*norm[u1] : 0.f;
                __half2 h2 = __floats2half2_rn(a0, a1);
                val = *(uint32_t*)&h2;
            }
            g_ah2[i] = val;
        }
        if (tid < CH) {
            float inv = bn_gamma[tid] * rsqrtf(bn_var[tid] + 1e-5f);
            g_scale[tid] = inv;
            g_shift[tid] = (conv_b[tid] - bn_mean[tid]) * inv + bn_beta[tid];
        }
    }
    for (int i = gtid; i < CH*36; i += gstride) {
        int co = i / 36, q = i % 36;
        uint32_t val = 0;
        if (q < 32) {
            __half2 h2 = __floats2half2_rn(gcn_w[(2*q)*CH + co], gcn_w[(2*q+1)*CH + co]);
            val = *(uint32_t*)&h2;
        }
        g_gw2[i] = val;
    }
    for (int i = gtid; i < KT*CH*36; i += gstride) {
        int k   = i / (CH*36);
        int rem = i - k*(CH*36);
        int co  = rem / 36;
        int p   = rem % 36;
        uint32_t val = 0;
        if (p < 32) {
            float w0 = conv_w[(co*CH + 2*p    )*KT + k];
            float w1 = conv_w[(co*CH + 2*p + 1)*KT + k];
            __half2 h2 = __floats2half2_rn(w0, w1);
            val = *(uint32_t*)&h2;
        }
        g_w2[i] = val;
    }
}

// ============================ fused GCN + Conv ============================
// smem: invariants [Ws2 9216B | ah2 2560B | gb 256B] = 12032B, then scratch union:
//   GCN: hs2 (128*36 u32 = 18432B) + hwT (256*20 u32 = 20480B)
//   Conv: xs (168*72 half = 24192B) + wb (2*64*36 u32 = 18432B)   -> union 42624B
#define HS_STR 36
#define WS_STR 36
#define HWT_STR 20
#define AH_STR 20
#define XSTR_H 72
#define WSTR_U 36
#define XROWS 168
#define INV_B 12032
#define SCRATCH_B 42624
#define FUSED_SMEM (INV_B + SCRATCH_B)   // 54656

__global__ __launch_bounds__(FUSED_THREADS, 3)
void fused_kernel(const float* __restrict__ h,
                  const float* __restrict__ gcn_b,
                  float* __restrict__ out) {
    extern __shared__ __align__(16) char smraw[];
    uint32_t* Ws2 = (uint32_t*)smraw;                       // 64*36
    uint32_t* ah2 = Ws2 + CH*WS_STR;                        // 32*20
    float*    gb  = (float*)(ah2 + 32*AH_STR);              // 64
    char*     scr = smraw + INV_B;
    uint32_t* hs2 = (uint32_t*)scr;                         // GCN
    uint32_t* hwT = (uint32_t*)(scr + 128*HS_STR*4);        // GCN
    __half*   xs  = (__half*)scr;                           // Conv
    uint32_t* wb  = (uint32_t*)(scr + XROWS*XSTR_H*2);      // Conv
    __shared__ int s_task;

    const int tid = threadIdx.x;
    const int lane = tid & 31, w = tid >> 5;
    const int gID = lane >> 2, tig = lane & 3;

    // invariants once per block
    for (int i = tid; i < CH*WS_STR/4; i += FUSED_THREADS)
        cp_async16(&Ws2[i*4], &g_gw2[i*4]);
    for (int i = tid; i < 32*AH_STR/4; i += FUSED_THREADS)
        cp_async16(&ah2[i*4], &g_ah2[i*4]);
    if (tid < 16)
        cp_async16(&gb[tid*4], &gcn_b[tid*4]);
    CP_COMMIT();
    CP_WAIT0();

    // conv per-lane constants (fixed smem addrs)
    const uint32_t xs32 = (uint32_t)__cvta_generic_to_shared(xs);
    const uint32_t wb32 = (uint32_t)__cvta_generic_to_shared(wb);
    const int xrow = ((lane >> 3) & 1) * 8 + (lane & 7);
    const int xkof = (lane >> 4) * 8;
    const uint32_t xbase = xs32 + (uint32_t)(((w*32 + xrow)*XSTR_H + xkof) * 2);
    const int bco  = (lane & 7) + ((lane >> 4) << 3);
    const int bkof = ((lane >> 3) & 1) * 4;
    const uint32_t bbase = wb32 + (uint32_t)((bco*WSTR_U + bkof) * 4);

    while (true) {
        if (tid == 0) s_task = (int)atomicAdd(&g_task, 1u);
        __syncthreads();                 // claim visible + prior task's smem use done
        const int t = s_task;
        if (t >= T_TOT) break;

        // ---- decode interleaved stream ----
        // t<75: GCN group t. Else seg/r: r<50 -> conv unit seg*50+r; else GCN 75+seg*75+(r-50).
        bool isconv;
        int id;
        if (t < 75) { isconv = false; id = t; }
        else {
            int u = t - 75, seg = u / 125, r = u - seg*125;
            if (seg >= 31)      { isconv = true;  id = 1550 + (u - 31*125); }
            else if (r < 50)    { isconv = true;  id = seg*50 + r; }
            else                { isconv = false; id = 75 + seg*75 + (r - 50); }
        }

        if (!isconv) {
            // ================= GCN group id (4 skeletons) =================
            const int g0 = id * 4;
            const int nmi = id / 75;
            const float* hbase = h + (long long)g0 * VJ * CH;

            // hs2 fill, all 128 rows (pads zeroed)
            for (int i = tid; i < 128*16; i += FUSED_THREADS) {
                int r = i >> 4, c4 = (i & 15) * 4;
                int s = r >> 5, vv = r & 31;
                uint2 val = make_uint2(0, 0);
                if (vv < VJ) {
                    float4 v = *(const float4*)&hbase[(s*VJ + vv)*CH + c4];
                    __half2 p0 = __floats2half2_rn(v.x, v.y);
                    __half2 p1 = __floats2half2_rn(v.z, v.w);
                    val = make_uint2(*(uint32_t*)&p0, *(uint32_t*)&p1);
                }
                *(uint2*)&hs2[r*HS_STR + (i & 15)*2] = val;
            }
            __syncthreads();

            // GEMM1' (fp16): hwT = W^T @ h^T; 8 tiles strided over 5 warps
            for (int mn = w; mn < 8; mn += 5) {
                const int mt = mn & 3, ng = mn >> 2;
                float acc[8][4];
#pragma unroll
                for (int nb = 0; nb < 8; nb++)
#pragma unroll
                    for (int j = 0; j < 4; j++) acc[nb][j] = 0.f;
#pragma unroll
                for (int kk = 0; kk < 4; kk++) {
                    int abase = (mt*16 + gID)*WS_STR + kk*8 + tig;
                    uint32_t a[4];
                    a[0] = Ws2[abase];
                    a[1] = Ws2[abase + 8*WS_STR];
                    a[2] = Ws2[abase + 4];
                    a[3] = Ws2[abase + 8*WS_STR + 4];
                    const uint32_t* bp = hs2 + (ng*64 + gID)*HS_STR + kk*8 + tig;
#pragma unroll
                    for (int nb = 0; nb < 8; nb++) {
                        uint32_t b0 = bp[nb*8*HS_STR];
                        uint32_t b1 = bp[nb*8*HS_STR + 4];
                        mma_f16(acc[nb], a, b0, b1);
                    }
                }
#pragma unroll
                for (int nb = 0; nb < 8; nb++) {
                    int srow = (ng*2 + (nb >> 2)) * 64 + mt*16 + gID;
                    int col  = (nb & 3)*4 + tig;
#pragma unroll
                    for (int rr = 0; rr < 2; rr++) {
                        __half2 h2 = __floats2half2_rn(acc[nb][rr*2], acc[nb][rr*2+1]);
                        hwT[(srow + rr*8)*HWT_STR + col] = *(uint32_t*)&h2;
                    }
                }
            }
            __syncthreads();

            // GEMM2 (fp16): x = Ah @ hw; 8 tasks strided over 5 warps
            for (int tt = w; tt < 8; tt += 5) {
                const int s = tt >> 1, mt2 = tt & 1;
                float acc[8][4];
#pragma unroll
                for (int nb = 0; nb < 8; nb++)
#pragma unroll
                    for (int j = 0; j < 4; j++) acc[nb][j] = 0.f;
#pragma unroll
                for (int kk = 0; kk < 2; kk++) {
                    int abase = (mt2*16 + gID)*AH_STR + kk*8 + tig;
                    uint32_t a[4];
                    a[0] = ah2[abase];
                    a[1] = ah2[abase + 8*AH_STR];
                    a[2] = ah2[abase + 4];
                    a[3] = ah2[abase + 8*AH_STR + 4];
                    const uint32_t* bp = hwT + (s*64 + gID)*HWT_STR + kk*8 + tig;
#pragma unroll
                    for (int nb = 0; nb < 8; nb++) {
                        uint32_t b0 = bp[nb*8*HWT_STR];
                        uint32_t b1 = bp[nb*8*HWT_STR + 4];
                        mma_f16(acc[nb], a, b0, b1);
                    }
                }
                const int g = g0 + s;
                const int nm = g / TLEN, tg2 = g % TLEN;
#pragma unroll
                for (int nb = 0; nb < 8; nb++) {
                    int c = nb*8 + tig*2;
                    float2 gbv = *(const float2*)&gb[c];
#pragma unroll
                    for (int rr = 0; rr < 2; rr++) {
                        int vv = mt2*16 + gID + rr*8;
                        if (vv < VJ) {
                            float x0 = fmaxf(acc[nb][rr*2]   + gbv.x, 0.f);
                            float x1 = fmaxf(acc[nb][rr*2+1] + gbv.y, 0.f);
                            __half2 h2 = __floats2half2_rn(x0, x1);
                            *(__half2*)&g_xg[((nm*VJ + vv)*TLEN + tg2)*CH + c] = h2;
                        }
                    }
                }
            }
            // publish: all stores visible, then release-count this group
            __threadfence();
            __syncthreads();
            if (tid == 0)
                asm volatile("red.release.gpu.global.add.u32 [%0], %1;"
                             :: "l"(&g_done[nmi]), "r"(1u) : "memory");
        } else {
            // ================= Conv unit id =================
            const int unit = id;
            const int slab = unit >> 1, half = unit & 1;
            const int nm = slab / VJ, v = slab % VJ;
            const int tbase = half * 150;

            if (tid == 0) {
                while (ld_acquire(&g_done[nm]) < 75u) __nanosleep(64);
            }
            __syncthreads();

            const __half* xg = g_xg + (long long)slab * TLEN * CH;
            // fill X + W tap0
            for (int i = tid; i < XROWS*8; i += FUSED_THREADS) {
                int r = i >> 3, c8 = (i & 7) * 8;
                int tg = tbase - 4 + r;
                __half* dst = &xs[r*XSTR_H + c8];
                if (r < 158 && tg >= 0 && tg < TLEN)
                    cp_async16(dst, xg + tg*CH + c8);
                else
                    *(float4*)dst = make_float4(0,0,0,0);
            }
            for (int i = tid; i < CH*WSTR_U/4; i += FUSED_THREADS)
                cp_async16(&wb[i*4], &g_w2[i*4]);
            CP_COMMIT();
            CP_WAIT0();
            __syncthreads();

            float acc[2][8][4];
#pragma unroll
            for (int mt = 0; mt < 2; mt++)
#pragma unroll
                for (int nb = 0; nb < 8; nb++)
#pragma unroll
                    for (int j = 0; j < 4; j++) acc[mt][nb][j] = 0.f;

            for (int k = 0; k < KT; k++) {
                const uint32_t wsel = (uint32_t)((k & 1) * (CH*WSTR_U*4));
                if (k < KT-1) {
                    uint32_t* wnext = wb + ((k+1) & 1) * CH*WSTR_U;
                    const uint32_t* wsrc = g_w2 + (k+1)*CH*WSTR_U;
                    for (int i = tid; i < CH*WSTR_U/4; i += FUSED_THREADS)
                        cp_async16(&wnext[i*4], &wsrc[i*4]);
                    CP_COMMIT();
                }
                const uint32_t xk = xbase + (uint32_t)(k * (XSTR_H*2));
#pragma unroll
                for (int kk = 0; kk < 4; kk++) {
                    uint32_t a0[4], a1[4];
                    ldsm_x4(a0, xk + kk*32);
                    ldsm_x4(a1, xk + 16*(XSTR_H*2) + kk*32);
                    uint32_t bf[4][4];
#pragma unroll
                    for (int p = 0; p < 4; p++)
                        ldsm_x4(bf[p], bbase + wsel + p*(16*WSTR_U*4) + kk*32);
#pragma unroll
                    for (int nb = 0; nb < 8; nb++) {
                        uint32_t b0 = bf[nb >> 1][(nb & 1)*2 + 0];
                        uint32_t b1 = bf[nb >> 1][(nb & 1)*2 + 1];
                        mma_f16(acc[0][nb], a0, b0, b1);
                        mma_f16(acc[1][nb], a1, b0, b1);
                    }
                }
                if (k < KT-1) {
                    CP_WAIT0();
                    __syncthreads();
                }
            }

            // epilogue: BN fold + ReLU + residual
#pragma unroll
            for (int mt = 0; mt < 2; mt++) {
#pragma unroll
                for (int nb = 0; nb < 8; nb++) {
                    int co = nb*8 + tig*2;
                    float2 scl = *(const float2*)&g_scale[co];
                    float2 sft = *(const float2*)&g_shift[co];
#pragma unroll
                    for (int rr = 0; rr < 2; rr++) {
                        int tl = w*32 + mt*16 + gID + rr*8;
                        if (tl >= 150) continue;
                        int tt2 = tbase + tl;
                        long long o = (((long long)nm*TLEN + tt2)*VJ + v)*CH + co;
                        float x0 = fmaxf(acc[mt][nb][rr*2]  *scl.x + sft.x, 0.f);
                        float x1 = fmaxf(acc[mt][nb][rr*2+1]*scl.y + sft.y, 0.f);
                        float2 hv = *(const float2*)&h[o];
                        *(float2*)&out[o] = make_float2(x0 + hv.x, x1 + hv.y);
                    }
                }
            }
        }
    }
}

// ============================ launch ============================
extern "C" void kernel_launch(void* const* d_in, const int* in_sizes, int n_in,
                              void* d_out, int out_size) {
    const float* h        = (const float*)d_in[0];
    const float* adj      = (const float*)d_in[1];
    const float* gcn_w    = (const float*)d_in[2];
    const float* gcn_b    = (const float*)d_in[3];
    const float* conv_w   = (const float*)d_in[4];
    const float* conv_b   = (const float*)d_in[5];
    const float* bn_gamma = (const float*)d_in[6];
    const float* bn_beta  = (const float*)d_in[7];
    const float* bn_mean  = (const float*)d_in[8];
    const float* bn_var   = (const float*)d_in[9];
    float* out = (float*)d_out;

    cudaFuncSetAttribute(fused_kernel, cudaFuncAttributeMaxDynamicSharedMemorySize, FUSED_SMEM);

    prep_kernel<<<256, 256>>>(adj, gcn_w, conv_w, conv_b, bn_gamma, bn_beta, bn_mean, bn_var);
    fused_kernel<<<FUSED_GRID, FUSED_THREADS, FUSED_SMEM>>>(h, gcn_b, out);
}

// round 15
// speedup vs baseline: 1.3857x; 1.3857x over previous
#include <cuda_runtime.h>
#include <cuda_fp16.h>
#include <cstdint>

// Problem constants
#define NMB 32          // N*M
#define TLEN 300
#define VJ 25
#define CH 64
#define KT 9
#define NSKEL (NMB*TLEN)          // 9600 skeletons

// -------- scratch --------
__device__ __half g_xg[NMB*VJ*TLEN*CH];            // GCN output (nm,v,t,c), fp16
__device__ __align__(16) uint32_t g_w2[KT*CH*36];  // conv W packed [tap][co][p(ci/2)] half2
__device__ __align__(16) uint32_t g_gw2[CH*36];    // GCN W packed [co][q(ci/2)] half2
__device__ __align__(16) uint32_t g_ah2[32*20];    // normalized adjacency fp16 [v][u-pair], padded
__device__ float g_scale[CH];                      // BN fold: gamma/sqrt(var+eps)
__device__ float g_shift[CH];                      // (conv_b - mean)*scale + beta

__device__ __forceinline__ void cp_async16(void* dst_smem, const void* src) {
    uint32_t d = (uint32_t)__cvta_generic_to_shared(dst_smem);
    asm volatile("cp.async.ca.shared.global [%0], [%1], 16;" :: "r"(d), "l"(src));
}
#define CP_COMMIT() asm volatile("cp.async.commit_group;")
#define CP_WAIT0()  asm volatile("cp.async.wait_group 0;")

__device__ __forceinline__ void mma_f16(float* d, const uint32_t* a, uint32_t b0, uint32_t b1) {
    asm volatile("mma.sync.aligned.m16n8k16.row.col.f32.f16.f16.f32 "
        "{%0,%1,%2,%3}, {%4,%5,%6,%7}, {%8,%9}, {%0,%1,%2,%3};"
        : "+f"(d[0]), "+f"(d[1]), "+f"(d[2]), "+f"(d[3])
        : "r"(a[0]), "r"(a[1]), "r"(a[2]), "r"(a[3]), "r"(b0), "r"(b1));
}

__device__ __forceinline__ void ldsm_x4(uint32_t* r, uint32_t saddr) {
    asm volatile("ldmatrix.sync.aligned.m8n8.x4.shared.b16 {%0,%1,%2,%3}, [%4];"
        : "=r"(r[0]), "=r"(r[1]), "=r"(r[2]), "=r"(r[3]) : "r"(saddr));
}

// ============================ prep ============================
__global__ void prep_kernel(const float* __restrict__ adj,
                            const float* __restrict__ gcn_w,
                            const float* __restrict__ conv_w,
                            const float* __restrict__ conv_b,
                            const float* __restrict__ bn_gamma,
                            const float* __restrict__ bn_beta,
                            const float* __restrict__ bn_mean,
                            const float* __restrict__ bn_var) {
    const int tid = threadIdx.x;
    const int gtid = blockIdx.x * blockDim.x + tid;
    const int gstride = gridDim.x * blockDim.x;

    if (blockIdx.x == 0) {
        __shared__ float norm[VJ];
        if (tid < VJ) {
            float s = 0.f;
            for (int u = 0; u < VJ; u++) s += adj[tid*VJ + u];
            norm[tid] = rsqrtf(s);
        }
        __syncthreads();
        // Ah fp16 pack: g_ah2[v][q] = half2(Ah(v,2q), Ah(v,2q+1)), zero-padded to 32x20
        for (int i = tid; i < 32*20; i += blockDim.x) {
            int v = i / 20, q = i % 20;
            uint32_t val = 0;
            if (v < VJ && q < 16) {
                int u0 = 2*q, u1 = 2*q + 1;
                float a0 = (u0 < VJ) ? norm[v]*adj[v*VJ+u0]*norm[u0] : 0.f;
                float a1 = (u1 < VJ) ? norm[v]*adj[v*VJ+u1]*norm[u1] : 0.f;
                __half2 h2 = __floats2half2_rn(a0, a1);
                val = *(uint32_t*)&h2;
            }
            g_ah2[i] = val;
        }
        if (tid < CH) {
            float inv = bn_gamma[tid] * rsqrtf(bn_var[tid] + 1e-5f);
            g_scale[tid] = inv;
            g_shift[tid] = (conv_b[tid] - bn_mean[tid]) * inv + bn_beta[tid];
        }
    }
    for (int i = gtid; i < CH*36; i += gstride) {
        int co = i / 36, q = i % 36;
        uint32_t val = 0;
        if (q < 32) {
            __half2 h2 = __floats2half2_rn(gcn_w[(2*q)*CH + co], gcn_w[(2*q+1)*CH + co]);
            val = *(uint32_t*)&h2;
        }
        g_gw2[i] = val;
    }
    for (int i = gtid; i < KT*CH*36; i += gstride) {
        int k   = i / (CH*36);
        int rem = i - k*(CH*36);
        int co  = rem / 36;
        int p   = rem % 36;
        uint32_t val = 0;
        if (p < 32) {
            float w0 = conv_w[(co*CH + 2*p    )*KT + k];
            float w1 = conv_w[(co*CH + 2*p + 1)*KT + k];
            __half2 h2 = __floats2half2_rn(w0, w1);
            val = *(uint32_t*)&h2;
        }
        g_w2[i] = val;
    }
}

// ============================ GCN (all-fp16, staged coalesced epilogue) ============================
#define HS_STR 36       // u32 per hs2 row
#define WS_STR 36       // u32 per Ws2 row
#define HWT_STR 20      // u32 per hwT row
#define AH_STR 20
#define GCN_S 4
#define GCN_GRID 600
#define GCN_ITERS 4     // 600*4 = 2400 groups

__global__ __launch_bounds__(256, 4)
void gcn_kernel(const float* __restrict__ h,
                const float* __restrict__ gcn_b) {
    extern __shared__ __align__(16) char smraw[];
    uint32_t* hs2 = (uint32_t*)smraw;                 // 128*36 (reused as x-staging after GEMM1)
    uint32_t* Ws2 = hs2 + 128*HS_STR;                 // 64*36
    uint32_t* hwT = Ws2 + CH*WS_STR;                  // 256*20
    uint32_t* ah2 = hwT + 256*HWT_STR;                // 32*20
    float*    gb  = (float*)(ah2 + 32*AH_STR);        // 64

    const int tid = threadIdx.x;

    for (int i = tid; i < CH*WS_STR/4; i += 256)
        cp_async16(&Ws2[i*4], &g_gw2[i*4]);
    for (int i = tid; i < 32*AH_STR/4; i += 256)
        cp_async16(&ah2[i*4], &g_ah2[i*4]);
    if (tid < 16)
        cp_async16(&gb[tid*4], &gcn_b[tid*4]);
    CP_COMMIT();
    CP_WAIT0();

    const int lane = tid & 31, w = tid >> 5;
    const int gID = lane >> 2, tig = lane & 3;

    for (int it = 0; it < GCN_ITERS; it++) {
        const int g0 = (blockIdx.x + it*GCN_GRID) * GCN_S;
        const float* hbase = h + (long long)g0 * VJ * CH;

        // hs2 fill, all 128 rows (pads re-zeroed each iter; hs2 was clobbered by staging)
        for (int i = tid; i < 128*16; i += 256) {
            int r = i >> 4, c4 = (i & 15) * 4;
            int s = r >> 5, vv = r & 31;
            uint2 val = make_uint2(0, 0);
            if (vv < VJ) {
                float4 v = *(const float4*)&hbase[(s*VJ + vv)*CH + c4];
                __half2 p0 = __floats2half2_rn(v.x, v.y);
                __half2 p1 = __floats2half2_rn(v.z, v.w);
                val = make_uint2(*(uint32_t*)&p0, *(uint32_t*)&p1);
            }
            *(uint2*)&hs2[r*HS_STR + (i & 15)*2] = val;
        }
        __syncthreads();

        // ---- GEMM1' (fp16): hwT = W^T @ h^T, 8 balanced warps ----
        {
            const int mt = w & 3;
            const int ng = w >> 2;
            float acc[8][4];
#pragma unroll
            for (int nb = 0; nb < 8; nb++)
#pragma unroll
                for (int j = 0; j < 4; j++) acc[nb][j] = 0.f;
#pragma unroll
            for (int kk = 0; kk < 4; kk++) {
                int abase = (mt*16 + gID)*WS_STR + kk*8 + tig;
                uint32_t a[4];
                a[0] = Ws2[abase];
                a[1] = Ws2[abase + 8*WS_STR];
                a[2] = Ws2[abase + 4];
                a[3] = Ws2[abase + 8*WS_STR + 4];
                const uint32_t* bp = hs2 + (ng*64 + gID)*HS_STR + kk*8 + tig;
#pragma unroll
                for (int nb = 0; nb < 8; nb++) {
                    uint32_t b0 = bp[nb*8*HS_STR];
                    uint32_t b1 = bp[nb*8*HS_STR + 4];
                    mma_f16(acc[nb], a, b0, b1);
                }
            }
#pragma unroll
            for (int nb = 0; nb < 8; nb++) {
                int srow = (ng*2 + (nb >> 2)) * 64 + mt*16 + gID;
                int col  = (nb & 3)*4 + tig;
#pragma unroll
                for (int rr = 0; rr < 2; rr++) {
                    __half2 h2 = __floats2half2_rn(acc[nb][rr*2], acc[nb][rr*2+1]);
                    hwT[(srow + rr*8)*HWT_STR + col] = *(uint32_t*)&h2;
                }
            }
        }
        __syncthreads();   // GEMM1 hs2 reads done -> hs2 reusable as staging

        // ---- GEMM2 (fp16): x = Ah @ hw; stage to smem (conflict-free), not global ----
        {
            const int s = w >> 1, mt2 = w & 1;
            float acc[8][4];
#pragma unroll
            for (int nb = 0; nb < 8; nb++)
#pragma unroll
                for (int j = 0; j < 4; j++) acc[nb][j] = 0.f;
#pragma unroll
            for (int kk = 0; kk < 2; kk++) {
                int abase = (mt2*16 + gID)*AH_STR + kk*8 + tig;
                uint32_t a[4];
                a[0] = ah2[abase];
                a[1] = ah2[abase + 8*AH_STR];
                a[2] = ah2[abase + 4];
                a[3] = ah2[abase + 8*AH_STR + 4];
                const uint32_t* bp = hwT + (s*64 + gID)*HWT_STR + kk*8 + tig;
#pragma unroll
                for (int nb = 0; nb < 8; nb++) {
                    uint32_t b0 = bp[nb*8*HWT_STR];
                    uint32_t b1 = bp[nb*8*HWT_STR + 4];
                    mma_f16(acc[nb], a, b0, b1);
                }
            }
            // +bias, relu, pack; store to hs2 staging at (s*32+vv)*36 + nb*4 + tig
#pragma unroll
            for (int nb = 0; nb < 8; nb++) {
                int c = nb*8 + tig*2;
                float2 gbv = *(const float2*)&gb[c];
#pragma unroll
                for (int rr = 0; rr < 2; rr++) {
                    int vv = mt2*16 + gID + rr*8;
                    float x0 = fmaxf(acc[nb][rr*2]   + gbv.x, 0.f);
                    float x1 = fmaxf(acc[nb][rr*2+1] + gbv.y, 0.f);
                    __half2 h2 = __floats2half2_rn(x0, x1);
                    hs2[(s*32 + vv)*HS_STR + nb*4 + tig] = *(uint32_t*)&h2;
                }
            }
        }
        __syncthreads();

        // ---- coalesced copy: staging -> g_xg (STG.128 on 128B-aligned rows) ----
        for (int i = tid; i < 100*8; i += 256) {
            int r = i >> 3, chunk = i & 7;
            int s = r / VJ, vv = r - s*VJ;
            uint4 val = *(uint4*)&hs2[(s*32 + vv)*HS_STR + chunk*4];
            int g = g0 + s;
            int nm = g / TLEN, t = g % TLEN;
            *(uint4*)&g_xg[((nm*VJ + vv)*TLEN + t)*CH + chunk*8] = val;
        }
        if (it < GCN_ITERS-1)
            __syncthreads();   // staging reads done before next iteration's fill
    }
}

// ============================ Conv (fp16 MMA + ldmatrix) — R11 proven, frozen ============================
#define XSTR_H 72          // halves per X row
#define WSTR_U 36          // u32 per W co row
#define XROWS 168
#define CONV_THREADS 160

__global__ __launch_bounds__(CONV_THREADS, 3)
void conv_mma_kernel(const float* __restrict__ h, float* __restrict__ out) {
    extern __shared__ __align__(16) char smraw[];
    __half*   xs  = (__half*)smraw;                        // 168*72 halves
    uint32_t* wb  = (uint32_t*)(smraw + XROWS*XSTR_H*2);   // 2 * 64*36 u32

    const int tid  = threadIdx.x;
    const int bid  = blockIdx.x;
    const int slab = bid >> 1;
    const int half = bid & 1;
    const int nm = slab / VJ, v = slab % VJ;
    const int tbase = half * 150;
    const __half* xg = g_xg + (long long)slab * TLEN * CH;

    for (int i = tid; i < XROWS*8; i += CONV_THREADS) {
        int r = i >> 3, c8 = (i & 7) * 8;
        int tg = tbase - 4 + r;
        __half* dst = &xs[r*XSTR_H + c8];
        if (r < 158 && tg >= 0 && tg < TLEN)
            cp_async16(dst, xg + tg*CH + c8);
        else
            *(float4*)dst = make_float4(0,0,0,0);
    }
    for (int i = tid; i < CH*WSTR_U/4; i += CONV_THREADS)
        cp_async16(&wb[i*4], &g_w2[i*4]);
    CP_COMMIT();
    CP_WAIT0();
    __syncthreads();

    const int lane = tid & 31, w = tid >> 5;
    const int gID = lane >> 2, tig = lane & 3;

    const uint32_t xs32 = (uint32_t)__cvta_generic_to_shared(xs);
    const uint32_t wb32 = (uint32_t)__cvta_generic_to_shared(wb);
    const int xrow = ((lane >> 3) & 1) * 8 + (lane & 7);
    const int xkof = (lane >> 4) * 8;
    const uint32_t xbase = xs32 + (uint32_t)(((w*32 + xrow)*XSTR_H + xkof) * 2);
    const int bco  = (lane & 7) + ((lane >> 4) << 3);
    const int bkof = ((lane >> 3) & 1) * 4;
    const uint32_t bbase = wb32 + (uint32_t)((bco*WSTR_U + bkof) * 4);

    float acc[2][8][4];
#pragma unroll
    for (int mt = 0; mt < 2; mt++)
#pragma unroll
        for (int nb = 0; nb < 8; nb++)
#pragma unroll
            for (int j = 0; j < 4; j++) acc[mt][nb][j] = 0.f;

    for (int k = 0; k < KT; k++) {
        const uint32_t wsel = (uint32_t)((k & 1) * (CH*WSTR_U*4));
        if (k < KT-1) {
            uint32_t* wnext = wb + ((k+1) & 1) * CH*WSTR_U;
            const uint32_t* wsrc = g_w2 + (k+1)*CH*WSTR_U;
            for (int i = tid; i < CH*WSTR_U/4; i += CONV_THREADS)
                cp_async16(&wnext[i*4], &wsrc[i*4]);
            CP_COMMIT();
        }
        const uint32_t xk = xbase + (uint32_t)(k * (XSTR_H*2));
#pragma unroll
        for (int kk = 0; kk < 4; kk++) {
            uint32_t a0[4], a1[4];
            ldsm_x4(a0, xk + kk*32);
            ldsm_x4(a1, xk + 16*(XSTR_H*2) + kk*32);
            uint32_t bf[4][4];
#pragma unroll
            for (int p = 0; p < 4; p++)
                ldsm_x4(bf[p], bbase + wsel + p*(16*WSTR_U*4) + kk*32);
#pragma unroll
            for (int nb = 0; nb < 8; nb++) {
                uint32_t b0 = bf[nb >> 1][(nb & 1)*2 + 0];
                uint32_t b1 = bf[nb >> 1][(nb & 1)*2 + 1];
                mma_f16(acc[0][nb], a0, b0, b1);
                mma_f16(acc[1][nb], a1, b0, b1);
            }
        }
        if (k < KT-1) {
            CP_WAIT0();
            __syncthreads();
        }
    }

#pragma unroll
    for (int mt = 0; mt < 2; mt++) {
#pragma unroll
        for (int nb = 0; nb < 8; nb++) {
            int co = nb*8 + tig*2;
            float2 scl = *(const float2*)&g_scale[co];
            float2 sft = *(const float2*)&g_shift[co];
#pragma unroll
            for (int rr = 0; rr < 2; rr++) {
                int tl = w*32 + mt*16 + gID + rr*8;
                if (tl >= 150) continue;
                int t = tbase + tl;
                long long o = (((long long)nm*TLEN + t)*VJ + v)*CH + co;
                float x0 = fmaxf(acc[mt][nb][rr*2]  *scl.x + sft.x, 0.f);
                float x1 = fmaxf(acc[mt][nb][rr*2+1]*scl.y + sft.y, 0.f);
                float2 hv = *(const float2*)&h[o];
                *(float2*)&out[o] = make_float2(x0 + hv.x, x1 + hv.y);
            }
        }
    }
}

// ============================ launch ============================
extern "C" void kernel_launch(void* const* d_in, const int* in_sizes, int n_in,
                              void* d_out, int out_size) {
    const float* h        = (const float*)d_in[0];
    const float* adj      = (const float*)d_in[1];
    const float* gcn_w    = (const float*)d_in[2];
    const float* gcn_b    = (const float*)d_in[3];
    const float* conv_w   = (const float*)d_in[4];
    const float* conv_b   = (const float*)d_in[5];
    const float* bn_gamma = (const float*)d_in[6];
    const float* bn_beta  = (const float*)d_in[7];
    const float* bn_mean  = (const float*)d_in[8];
    const float* bn_var   = (const float*)d_in[9];
    float* out = (float*)d_out;

    const int gcn_smem  = (128*HS_STR + CH*WS_STR + 256*HWT_STR + 32*AH_STR)*4 + CH*4;  // ~51 KB
    const int conv_smem = XROWS*XSTR_H*2 + 2*CH*WSTR_U*4;      // 42624 B
    cudaFuncSetAttribute(gcn_kernel,      cudaFuncAttributeMaxDynamicSharedMemorySize, gcn_smem);
    cudaFuncSetAttribute(conv_mma_kernel, cudaFuncAttributeMaxDynamicSharedMemorySize, conv_smem);

    prep_kernel<<<256, 256>>>(adj, gcn_w, conv_w, conv_b, bn_gamma, bn_beta, bn_mean, bn_var);
    gcn_kernel<<<GCN_GRID, 256, gcn_smem>>>(h, gcn_b);
    conv_mma_kernel<<<NMB*VJ*2, CONV_THREADS, conv_smem>>>(h, out);
}